// round 4
// baseline (speedup 1.0000x reference)
#include <cuda_runtime.h>

// Problem constants
#define K_COLORS 512
#define CHUNK    32
#define NCHUNK   (K_COLORS / CHUNK)   // 16
#define HW       65536                // 256*256
#define B        8
#define PPT      4                    // pixels (batch images) per thread
#define NPAIR    (PPT / 2)
#define NTHREADS 128
#define NBLOCKS  1024                 // 131072 threads = HW * (B/PPT)
#define NPIX     (HW * B)             // 524288
#define NOUT     (NPIX * 3)           // 1572864

__device__ float        g_partials[NBLOCKS];
__device__ unsigned int g_count = 0;

// ---- packed f32x2 helpers (Blackwell PTX-only ops) ----
__device__ __forceinline__ unsigned long long fma2(unsigned long long a,
                                                   unsigned long long b,
                                                   unsigned long long c) {
    unsigned long long d;
    asm("fma.rn.f32x2 %0, %1, %2, %3;" : "=l"(d) : "l"(a), "l"(b), "l"(c));
    return d;
}
__device__ __forceinline__ unsigned long long pk2(float lo, float hi) {
    unsigned long long r;
    asm("mov.b64 %0, {%1, %2};" : "=l"(r)
        : "r"(__float_as_uint(lo)), "r"(__float_as_uint(hi)));
    return r;
}
__device__ __forceinline__ unsigned long long bc2(float x) {
    unsigned int u = __float_as_uint(x);
    return ((unsigned long long)u << 32) | u;
}
__device__ __forceinline__ float lo_f(unsigned long long v) {
    return __uint_as_float((unsigned int)v);
}
__device__ __forceinline__ float hi_f(unsigned long long v) {
    return __uint_as_float((unsigned int)(v >> 32));
}

// Fused VQ + straight-through output + loss.
//
// Inner loop tracks ONLY the min distance (3 fma2 + 2 FMNMX per pixel-pair
// per color = 5 ops, vs 9 when tracking the index inline). Index recovery is
// hierarchical and exact:
//   - per 32-color chunk, the chunk min is compared to the running best with
//     a strict '<' (first chunk wins ties -> matches jnp.argmin ordering);
//   - at the end, the winning chunk (32 colors) is rescanned per pixel with
//     the bit-identical scalar FMA chain and an exact '==' match; the first
//     match is the argmin index.
__global__ void __launch_bounds__(NTHREADS, 7) vq_kernel(
    const float* __restrict__ z,
    const float* __restrict__ table,
    float* __restrict__ out,
    int out_size)
{
    __shared__ ulonglong2 scA[K_COLORS];   // {(-2t0,-2t0),(-2t1,-2t1)}
    __shared__ ulonglong2 scB[K_COLORS];   // {(-2t2,-2t2),(n,n)}
    __shared__ float4     sc4[K_COLORS];   // (-2t0,-2t1,-2t2,n) for rescan
    __shared__ float      sred[NTHREADS];
    __shared__ int        s_last;

    const int tid = threadIdx.x;

    for (int k = tid; k < K_COLORS; k += NTHREADS) {
        float t0 = table[3 * k + 0];
        float t1 = table[3 * k + 1];
        float t2 = table[3 * k + 2];
        float n  = __fadd_rn(__fadd_rn(__fmul_rn(t0, t0), __fmul_rn(t1, t1)),
                             __fmul_rn(t2, t2));
        float a0 = -2.0f * t0, a1 = -2.0f * t1, a2 = -2.0f * t2;
        scA[k] = make_ulonglong2(bc2(a0), bc2(a1));
        scB[k] = make_ulonglong2(bc2(a2), bc2(n));
        sc4[k] = make_float4(a0, a1, a2, n);
    }
    __syncthreads();

    const int g    = blockIdx.x * NTHREADS + tid;   // 0..131071
    const int hw   = g & (HW - 1);
    const int bat0 = (g >> 16) * PPT;               // first batch image

    unsigned long long X[NPAIR], Y[NPAIR], Z[NPAIR];
#pragma unroll
    for (int j = 0; j < NPAIR; ++j) {
        const int bA = (bat0 + 2 * j)     * 3 * HW + hw;
        const int bB = (bat0 + 2 * j + 1) * 3 * HW + hw;
        X[j] = pk2(z[bA],          z[bB]);
        Y[j] = pk2(z[bA + HW],     z[bB + HW]);
        Z[j] = pk2(z[bA + 2 * HW], z[bB + 2 * HW]);
    }

    float gbest[PPT];
    int   gch[PPT];
#pragma unroll
    for (int p = 0; p < PPT; ++p) { gbest[p] = 3.402823466e38f; gch[p] = 0; }

    for (int c = 0; c < NCHUNK; ++c) {
        float cm[PPT];
#pragma unroll
        for (int p = 0; p < PPT; ++p) cm[p] = 3.402823466e38f;

#pragma unroll 8
        for (int i = 0; i < CHUNK; ++i) {
            const int k = (c << 5) + i;
            const ulonglong2 ca = scA[k];
            const ulonglong2 cb = scB[k];
#pragma unroll
            for (int j = 0; j < NPAIR; ++j) {
                // d = x*(-2t0) + (y*(-2t1) + (z*(-2t2) + n))
                unsigned long long acc = fma2(Z[j], cb.x, cb.y);
                acc = fma2(Y[j], ca.y, acc);
                acc = fma2(X[j], ca.x, acc);
                cm[2 * j]     = fminf(cm[2 * j],     lo_f(acc));
                cm[2 * j + 1] = fminf(cm[2 * j + 1], hi_f(acc));
            }
        }
        // Chunk commit: strict '<' keeps the EARLIEST chunk on exact ties.
#pragma unroll
        for (int p = 0; p < PPT; ++p) {
            bool lt  = cm[p] < gbest[p];
            gbest[p] = fminf(gbest[p], cm[p]);
            gch[p]   = lt ? c : gch[p];
        }
    }

    // Exact index recovery inside the winning chunk (first '==' match).
    int bi[PPT];
#pragma unroll
    for (int p = 0; p < PPT; ++p) {
        const int kb = gch[p] << 5;
        const float fx = (p & 1) ? hi_f(X[p >> 1]) : lo_f(X[p >> 1]);
        const float fy = (p & 1) ? hi_f(Y[p >> 1]) : lo_f(Y[p >> 1]);
        const float fz = (p & 1) ? hi_f(Z[p >> 1]) : lo_f(Z[p >> 1]);
        int found = 1023;
#pragma unroll 8
        for (int i = 0; i < CHUNK; ++i) {
            const float4 cc = sc4[kb + i];
            float d = fmaf(fx, cc.x, fmaf(fy, cc.y, fmaf(fz, cc.z, cc.w)));
            int kc = (d == gbest[p]) ? (kb + i) : 1023;
            found  = min(found, kc);
        }
        bi[p] = found;
    }

    // Epilogue: exact color from -2t (x -0.5 is exact), reference STE
    // rounding, squared-error accumulation.
    float lsum = 0.0f;
#pragma unroll
    for (int p = 0; p < PPT; ++p) {
        const float4 cc = sc4[bi[p]];
        float q0 = -0.5f * cc.x;
        float q1 = -0.5f * cc.y;
        float q2 = -0.5f * cc.z;
        float px = (p & 1) ? hi_f(X[p >> 1]) : lo_f(X[p >> 1]);
        float py = (p & 1) ? hi_f(Y[p >> 1]) : lo_f(Y[p >> 1]);
        float pz = (p & 1) ? hi_f(Z[p >> 1]) : lo_f(Z[p >> 1]);
        float d0 = __fsub_rn(q0, px);
        float d1 = __fsub_rn(q1, py);
        float d2 = __fsub_rn(q2, pz);
        const int base = (bat0 + p) * 3 * HW + hw;
        out[base]          = __fadd_rn(px, d0);     // zl + (z_q - zl)
        out[base + HW]     = __fadd_rn(py, d1);
        out[base + 2 * HW] = __fadd_rn(pz, d2);
        lsum = fmaf(d0, d0, lsum);
        lsum = fmaf(d1, d1, lsum);
        lsum = fmaf(d2, d2, lsum);
    }

    // Deterministic block reduction.
    sred[tid] = lsum;
    __syncthreads();
#pragma unroll
    for (int s = NTHREADS / 2; s > 0; s >>= 1) {
        if (tid < s) sred[tid] += sred[tid + s];
        __syncthreads();
    }

    // Last-block-done final reduction (single fused kernel).
    if (tid == 0) {
        g_partials[blockIdx.x] = sred[0];
        __threadfence();
        unsigned int prev = atomicAdd(&g_count, 1u);
        s_last = (prev == NBLOCKS - 1) ? 1 : 0;
    }
    __syncthreads();

    if (s_last) {
        __threadfence();
        volatile float* vp = g_partials;
        float acc = 0.0f;
        for (int i = tid; i < NBLOCKS; i += NTHREADS) acc += vp[i];
        sred[tid] = acc;
        __syncthreads();
#pragma unroll
        for (int s = NTHREADS / 2; s > 0; s >>= 1) {
            if (tid < s) sred[tid] += sred[tid + s];
            __syncthreads();
        }
        if (tid == 0) {
            float m    = sred[0] / (float)NOUT;
            float loss = __fadd_rn(10.0f * m, m);
            for (int i = NOUT; i < out_size; ++i) out[i] = loss;
            g_count = 0;   // reset for the next graph replay
        }
    }
}

extern "C" void kernel_launch(void* const* d_in, const int* in_sizes, int n_in,
                              void* d_out, int out_size)
{
    const float* z     = (const float*)d_in[0];
    const float* table = (const float*)d_in[1];
    float* out         = (float*)d_out;

    vq_kernel<<<NBLOCKS, NTHREADS>>>(z, table, out, out_size);
}

// round 6
// speedup vs baseline: 1.1956x; 1.1956x over previous
#include <cuda_runtime.h>

// Problem constants
#define K_COLORS 512
#define CHUNK    32
#define NCHUNK   (K_COLORS / CHUNK)   // 16
#define GRP      (CHUNK / 4)          // 8 four-color groups per chunk
#define HW       65536                // 256*256
#define B        8
#define PPT      8                    // all 8 batch images per thread
#define NTHREADS 64
#define NBLOCKS  1024                 // 65536 threads = HW
#define NPIX     (HW * B)             // 524288
#define NOUT     (NPIX * 3)           // 1572864

__device__ float        g_partials[NBLOCKS];
__device__ unsigned int g_count = 0;

// ---- packed f32x2 helpers (Blackwell PTX ops) ----
__device__ __forceinline__ unsigned long long fma2(unsigned long long a,
                                                   unsigned long long b,
                                                   unsigned long long c) {
    unsigned long long d;
    asm("fma.rn.f32x2 %0, %1, %2, %3;" : "=l"(d) : "l"(a), "l"(b), "l"(c));
    return d;
}
__device__ __forceinline__ unsigned long long bc2(float x) {
    unsigned int u = __float_as_uint(x);
    return ((unsigned long long)u << 32) | u;
}
__device__ __forceinline__ float lo_f(unsigned long long v) {
    return __uint_as_float((unsigned int)v);
}
__device__ __forceinline__ float hi_f(unsigned long long v) {
    return __uint_as_float((unsigned int)(v >> 32));
}

// Fused VQ + straight-through output + loss.
//
// Palette stored SoA in smem (A0/A1/A2/N): ONE LDS.128 delivers one
// coefficient for FOUR consecutive colors as two f32x2 pairs, and that load
// is shared by all 8 pixels (4 B per color per thread vs 32 B in rounds 1-4,
// which were smem-wavefront bound at L1=76%). The PIXEL value is broadcast
// into both packed halves once, outside the k loop.
//
// Inner loop per 4 colors per pixel: 6 fma2 + 4 scalar fminf (no packed f32
// min exists on sm_103a). Value-only tracking; index recovery is hierarchical
// and exact (validated bit-for-bit in round 4):
//   - per 32-color chunk, strict '<' commit in ascending chunk order;
//   - winning chunk rescanned with the bit-identical scalar FMA chain,
//     first '==' match wins (jnp.argmin first-index semantics).
__global__ void __launch_bounds__(NTHREADS) vq_kernel(
    const float* __restrict__ z,
    const float* __restrict__ table,
    float* __restrict__ out,
    int out_size)
{
    __shared__ ulonglong2 sA0[K_COLORS / 4];  // a0 pairs: {(k,k+1),(k+2,k+3)}
    __shared__ ulonglong2 sA1[K_COLORS / 4];
    __shared__ ulonglong2 sA2[K_COLORS / 4];
    __shared__ ulonglong2 sNN[K_COLORS / 4];
    __shared__ float4     sc4[K_COLORS];      // (-2t0,-2t1,-2t2,n) for rescan
    __shared__ float      sred[NTHREADS];
    __shared__ int        s_last;

    const int tid = threadIdx.x;

    for (int k = tid; k < K_COLORS; k += NTHREADS) {
        float t0 = table[3 * k + 0];
        float t1 = table[3 * k + 1];
        float t2 = table[3 * k + 2];
        float n  = __fadd_rn(__fadd_rn(__fmul_rn(t0, t0), __fmul_rn(t1, t1)),
                             __fmul_rn(t2, t2));
        float a0 = -2.0f * t0, a1 = -2.0f * t1, a2 = -2.0f * t2;
        ((float*)sA0)[k] = a0;
        ((float*)sA1)[k] = a1;
        ((float*)sA2)[k] = a2;
        ((float*)sNN)[k] = n;
        sc4[k] = make_float4(a0, a1, a2, n);
    }
    __syncthreads();

    const int g = blockIdx.x * NTHREADS + tid;   // hw index, 0..65535

    // Pixel components broadcast into both packed halves (loop-invariant).
    unsigned long long Xb[PPT], Yb[PPT], Zb[PPT];
#pragma unroll
    for (int p = 0; p < PPT; ++p) {
        const int base = p * 3 * HW + g;
        Xb[p] = bc2(z[base]);
        Yb[p] = bc2(z[base + HW]);
        Zb[p] = bc2(z[base + 2 * HW]);
    }

    float gbest[PPT];
    int   gch[PPT];
#pragma unroll
    for (int p = 0; p < PPT; ++p) { gbest[p] = 3.402823466e38f; gch[p] = 0; }

    for (int c = 0; c < NCHUNK; ++c) {
        float cmlo[PPT], cmhi[PPT];
#pragma unroll
        for (int p = 0; p < PPT; ++p) {
            cmlo[p] = 3.402823466e38f;
            cmhi[p] = 3.402823466e38f;
        }

#pragma unroll 4
        for (int q = 0; q < GRP; ++q) {
            const int g4 = c * GRP + q;            // colors 4*g4 .. 4*g4+3
            const ulonglong2 a0 = sA0[g4];
            const ulonglong2 a1 = sA1[g4];
            const ulonglong2 a2 = sA2[g4];
            const ulonglong2 nn = sNN[g4];
#pragma unroll
            for (int p = 0; p < PPT; ++p) {
                // d = x*(-2t0) + (y*(-2t1) + (z*(-2t2) + n)) — same chain
                // order/rounding as the reference scalar fmaf chain.
                unsigned long long d01 =
                    fma2(Xb[p], a0.x, fma2(Yb[p], a1.x, fma2(Zb[p], a2.x, nn.x)));
                unsigned long long d23 =
                    fma2(Xb[p], a0.y, fma2(Yb[p], a1.y, fma2(Zb[p], a2.y, nn.y)));
                cmlo[p] = fminf(cmlo[p], fminf(lo_f(d01), lo_f(d23)));
                cmhi[p] = fminf(cmhi[p], fminf(hi_f(d01), hi_f(d23)));
            }
        }
        // Chunk commit: strict '<' keeps the EARLIEST chunk on exact ties.
#pragma unroll
        for (int p = 0; p < PPT; ++p) {
            float m  = fminf(cmlo[p], cmhi[p]);
            bool lt  = m < gbest[p];
            gbest[p] = fminf(gbest[p], m);
            gch[p]   = lt ? c : gch[p];
        }
    }

    // Exact index recovery (first '==' match inside the winning chunk),
    // fused with the STE epilogue + loss accumulation.
    float lsum = 0.0f;
#pragma unroll
    for (int p = 0; p < PPT; ++p) {
        const int   kb = gch[p] << 5;
        const float px = lo_f(Xb[p]);
        const float py = lo_f(Yb[p]);
        const float pz = lo_f(Zb[p]);
        int found = 1023;
#pragma unroll 8
        for (int i = 0; i < CHUNK; ++i) {
            const float4 cc = sc4[kb + i];
            float d = fmaf(px, cc.x, fmaf(py, cc.y, fmaf(pz, cc.z, cc.w)));
            int kc = (d == gbest[p]) ? (kb + i) : 1023;
            found  = min(found, kc);
        }
        const float4 cc = sc4[found];
        float q0 = -0.5f * cc.x;                 // exact recovery of t from -2t
        float q1 = -0.5f * cc.y;
        float q2 = -0.5f * cc.z;
        float d0 = __fsub_rn(q0, px);
        float d1 = __fsub_rn(q1, py);
        float d2 = __fsub_rn(q2, pz);
        const int base = p * 3 * HW + g;
        out[base]          = __fadd_rn(px, d0);  // zl + (z_q - zl)
        out[base + HW]     = __fadd_rn(py, d1);
        out[base + 2 * HW] = __fadd_rn(pz, d2);
        lsum = fmaf(d0, d0, lsum);
        lsum = fmaf(d1, d1, lsum);
        lsum = fmaf(d2, d2, lsum);
    }

    // Deterministic block reduction.
    sred[tid] = lsum;
    __syncthreads();
#pragma unroll
    for (int s = NTHREADS / 2; s > 0; s >>= 1) {
        if (tid < s) sred[tid] += sred[tid + s];
        __syncthreads();
    }

    // Last-block-done final reduction (single fused kernel).
    if (tid == 0) {
        g_partials[blockIdx.x] = sred[0];
        __threadfence();
        unsigned int prev = atomicAdd(&g_count, 1u);
        s_last = (prev == NBLOCKS - 1) ? 1 : 0;
    }
    __syncthreads();

    if (s_last) {
        __threadfence();
        volatile float* vp = g_partials;
        float acc = 0.0f;
        for (int i = tid; i < NBLOCKS; i += NTHREADS) acc += vp[i];
        sred[tid] = acc;
        __syncthreads();
#pragma unroll
        for (int s = NTHREADS / 2; s > 0; s >>= 1) {
            if (tid < s) sred[tid] += sred[tid + s];
            __syncthreads();
        }
        if (tid == 0) {
            float m    = sred[0] / (float)NOUT;
            float loss = __fadd_rn(10.0f * m, m);
            for (int i = NOUT; i < out_size; ++i) out[i] = loss;
            g_count = 0;   // reset for the next graph replay
        }
    }
}

extern "C" void kernel_launch(void* const* d_in, const int* in_sizes, int n_in,
                              void* d_out, int out_size)
{
    const float* z     = (const float*)d_in[0];
    const float* table = (const float*)d_in[1];
    float* out         = (float*)d_out;

    vq_kernel<<<NBLOCKS, NTHREADS>>>(z, table, out, out_size);
}